// round 13
// baseline (speedup 1.0000x reference)
#include <cuda_runtime.h>
#include <cstdint>

#define Bc   16
#define NFc  16
#define Nc   1024
#define Dc   128
#define Sc   8
#define Hc   128
#define BSc  (Bc*Sc)          // 128
#define NCHUNK 32
#define CHTOK  32
#define NBLK  512             // NCHUNK * Bc
#define SCALEc 0.08838834764831845f
#define EPSc   1e-8f

// ---------------- device scratch ----------------
__device__ float g_qt[BSc*Dc];
__device__ float g_qb[BSc];
__device__ float g_slots[BSc*Dc];
__device__ float g_Yapart[NCHUNK*BSc*Dc];
__device__ float g_rspart[NCHUNK*BSc];
__device__ float g_WcT[Dc*3*Dc];
__device__ float g_bc[3*Dc];
__device__ float g_WhhT[Dc*3*Dc];
__device__ float g_W1T[Dc*Hc];
__device__ float g_W2T[Hc*Dc];
__device__ float g_MT[Dc*Dc];
__device__ float g_qtb[Dc];
__device__ float g_qbv[Dc];
__device__ float g_qbb[1];

// grid barrier state (gen monotonically increases across graph replays; cnt returns to 0)
__device__ unsigned g_cnt;
__device__ volatile unsigned g_gen;

// ---------------- helpers ----------------
__device__ __forceinline__ float sigmoidf_(float x) { return 1.0f / (1.0f + expf(-x)); }

__device__ __forceinline__ void grid_barrier() {
    __syncthreads();
    if (threadIdx.x == 0) {
        __threadfence();
        unsigned gen = g_gen;
        if (atomicAdd(&g_cnt, 1u) == NBLK - 1) {
            g_cnt = 0;
            __threadfence();
            g_gen = gen + 1;
        } else {
            while (g_gen == gen) { __nanosleep(64); }
        }
        __threadfence();
    }
    __syncthreads();
}

__device__ __forceinline__ float bsum256(float v, float* red) {
    #pragma unroll
    for (int o = 16; o; o >>= 1) v += __shfl_xor_sync(0xffffffffu, v, o);
    int t = threadIdx.x;
    if ((t & 31) == 0) red[t >> 5] = v;
    __syncthreads();
    float r = red[0] + red[1] + red[2] + red[3] + red[4] + red[5] + red[6] + red[7];
    __syncthreads();
    return r;
}

// ---------------- prep: transposes, folded matrices, bias vectors -------
__global__ void prep_kernel(const float* __restrict__ Wq, const float* __restrict__ bq,
                            const float* __restrict__ Wk, const float* __restrict__ bk,
                            const float* __restrict__ W1, const float* __restrict__ W2,
                            const float* __restrict__ Wih, const float* __restrict__ Whh,
                            const float* __restrict__ Wv, const float* __restrict__ bv) {
    int blk = blockIdx.x;
    int t = threadIdx.x;
    if (blk < 192) {
        int idx = blk * 256 + t;
        int j = idx >> 7, d = idx & 127;
        g_WhhT[d * 384 + j] = Whh[idx];
        if (idx < Dc * Dc) {
            int r = idx >> 7, c = idx & 127;
            g_W1T[c * Dc + r] = W1[idx];
            g_W2T[c * Dc + r] = W2[idx];
        }
    } else if (blk == 192) {
        if (t < 128) {
            float aq = 0.0f, ab = 0.0f;
            for (int j = 0; j < 128; j++) {
                aq += Wq[j * 128 + t] * bk[j];
                ab += Wk[j * 128 + t] * bq[j];
            }
            g_qbv[t] = aq;
            g_qtb[t] = ab;
            if (t == 0) {
                float s = 0.0f;
                for (int j = 0; j < 128; j++) s += bq[j] * bk[j];
                g_qbb[0] = s;
            }
        }
        for (int j = t; j < 384; j += 256) {
            float s = 0.0f;
            for (int d = 0; d < 128; d++) s += Wih[j * 128 + d] * bv[d];
            g_bc[j] = s;
        }
    } else if (blk < 577) {
        __shared__ float row[128];
        int j = blk - 193;
        if (t < 128) row[t] = Wih[j * 128 + t];
        __syncthreads();
        if (t < 128) {
            float s = 0.0f;
            #pragma unroll 8
            for (int d = 0; d < 128; d++) s += row[d] * Wv[d * 128 + t];
            g_WcT[t * 384 + j] = s;
        }
    } else {
        int e = blk - 577;
        if (t < 128) {
            float s = 0.0f;
            #pragma unroll 8
            for (int j = 0; j < 128; j++) s += Wk[j * 128 + t] * Wq[j * 128 + e];
            g_MT[e * 128 + t] = s;
        }
    }
}

// ---------------- persistent main kernel --------------------------------
#define XST 132
#define ASTB 33
// shared overlay: stepB needs 4224+1056+264+8 = 5552; stepC needs < 2000
#define SMF 5560
__global__ void __launch_bounds__(256) main_kernel(
        const float* __restrict__ x, const float* __restrict__ slots_init,
        float* __restrict__ out_slots, float* __restrict__ out_attn,
        const float* __restrict__ bih, const float* __restrict__ bhh,
        const float* __restrict__ g_ff, const float* __restrict__ be_ff,
        const float* __restrict__ b1, const float* __restrict__ b2,
        const float* __restrict__ g_sl, const float* __restrict__ be_sl,
        const float* __restrict__ g_in, const float* __restrict__ be_in) {
    __shared__ float sm[SMF];
    const int t = threadIdx.x;
    const int lane = t & 31, w = t >> 5;
    const int bid = blockIdx.x;
    const int chunk = bid & 31;
    const int b = bid >> 5;

    // ---- init phase: blocks 0..127 compute slots + first qt/qb ----
    if (bid < BSc) {
        const int bs = bid;
        const int s = bs & 7;
        float* lnv = sm;             // 128
        float* part = sm + 128;      // 256
        float* red = sm + 384;       // 8
        float v = 0.0f;
        if (t < 128) {
            v = slots_init[s * Dc + t];
            g_slots[bs * Dc + t] = v;
        }
        float m = bsum256(v, red) * (1.0f / 128.0f);
        float dx = (t < 128) ? (v - m) : 0.0f;
        float var = bsum256(dx * dx, red) * (1.0f / 128.0f);
        if (t < 128) lnv[t] = dx * rsqrtf(var + 1e-5f) * g_sl[t] + be_sl[t];
        __syncthreads();
        {
            int col = t & 127, h2 = t >> 7;
            float acc = 0.0f;
            #pragma unroll 8
            for (int i = 0; i < 64; i++) {
                int e = h2 * 64 + i;
                acc += g_MT[e * 128 + col] * lnv[e];
            }
            part[h2 * 128 + col] = acc;
        }
        __syncthreads();
        if (t < 128) g_qt[bs * Dc + t] = part[t] + part[128 + t] + g_qtb[t];
        float qv = (t < 128) ? (g_qbv[t] * lnv[t]) : 0.0f;
        float qb = bsum256(qv, red);
        if (t == 0) g_qb[bs] = qb + g_qbb[0];
    }
    grid_barrier();

    float4 gg = ((const float4*)g_in)[lane];
    float4 bb = ((const float4*)be_in)[lane];

    for (int step = 0; step <= NFc; step++) {
        const int f = (step == 0) ? 0 : step - 1;
        const int emit = (step > 0) ? 1 : 0;

        // ================= stepB: all 512 blocks =================
        {
            float* xs  = sm;                       // 32*132
            float* qts = sm + CHTOK * XST;         // 8*132
            float* as  = qts + Sc * XST;           // 8*33
            float* qbs = as + Sc * ASTB;           // 8
            const int bf = b * NFc + f;
            const float* xg = x + ((size_t)bf * Nc + (size_t)chunk * CHTOK) * Dc;

            #pragma unroll
            for (int r = w; r < CHTOK; r += 8) {
                float4 v = ((const float4*)(xg + r * Dc))[lane];
                float s = v.x + v.y + v.z + v.w;
                #pragma unroll
                for (int o = 16; o; o >>= 1) s += __shfl_xor_sync(0xffffffffu, s, o);
                float m = s * (1.0f / 128.0f);
                float d0 = v.x - m, d1 = v.y - m, d2 = v.z - m, d3 = v.w - m;
                float ss = d0*d0 + d1*d1 + d2*d2 + d3*d3;
                #pragma unroll
                for (int o = 16; o; o >>= 1) ss += __shfl_xor_sync(0xffffffffu, ss, o);
                float inv = rsqrtf(ss * (1.0f / 128.0f) + 1e-5f);
                float* xr = xs + r * XST + lane * 4;
                xr[0] = d0 * inv * gg.x + bb.x;
                xr[1] = d1 * inv * gg.y + bb.y;
                xr[2] = d2 * inv * gg.z + bb.z;
                xr[3] = d3 * inv * gg.w + bb.w;
            }
            {
                int s = t >> 5, dq = (t & 31) * 4;
                *(float4*)(qts + s * XST + dq) = *(const float4*)(g_qt + (b * Sc + s) * Dc + dq);
            }
            if (t < 8) qbs[t] = g_qb[b * Sc + t];
            __syncthreads();

            const int tt = t >> 3;
            const int s = t & 7;
            float dot = 0.0f;
            const float* qrow = qts + s * XST;
            const float* xrow = xs + tt * XST;
            #pragma unroll 8
            for (int j = 0; j < 32; j++) {
                float4 q4 = *(const float4*)(qrow + j * 4);
                float4 x4 = *(const float4*)(xrow + j * 4);
                dot += q4.x*x4.x + q4.y*x4.y + q4.z*x4.z + q4.w*x4.w;
            }
            dot = (dot + qbs[s]) * SCALEc;
            float mx = dot;
            #pragma unroll
            for (int o = 4; o; o >>= 1) mx = fmaxf(mx, __shfl_xor_sync(0xffffffffu, mx, o));
            float e = expf(dot - mx);
            float es = e;
            #pragma unroll
            for (int o = 4; o; o >>= 1) es += __shfl_xor_sync(0xffffffffu, es, o);
            float a = e / es + EPSc;
            as[s * ASTB + tt] = a;
            __syncthreads();

            if (emit) {
                int s3 = t >> 5, n3 = t & 31;
                out_attn[(size_t)bf * Sc * Nc + (size_t)s3 * Nc + chunk * CHTOK + n3] = as[s3 * ASTB + n3];
            }
            {
                float rs = as[w * ASTB + lane];
                #pragma unroll
                for (int o = 16; o; o >>= 1) rs += __shfl_xor_sync(0xffffffffu, rs, o);
                if (lane == 0) g_rspart[chunk * BSc + b * Sc + w] = rs;
            }
            {
                float4 up = make_float4(0.f, 0.f, 0.f, 0.f);
                const float* arow = as + w * ASTB;
                #pragma unroll 8
                for (int n = 0; n < CHTOK; n++) {
                    float a2 = arow[n];
                    float4 v4 = *(const float4*)(xs + n * XST + lane * 4);
                    up.x += a2 * v4.x; up.y += a2 * v4.y;
                    up.z += a2 * v4.z; up.w += a2 * v4.w;
                }
                *(float4*)(g_Yapart + (size_t)(chunk * BSc + b * Sc + w) * Dc + lane * 4) = up;
            }
        }
        grid_barrier();

        // ================= stepC: blocks 0..127, one bs each =================
        if (bid < BSc) {
            const int bs = bid;
            float* yn   = sm;            // 128
            float* hs   = sm + 128;      // 128
            float* hgs  = sm + 256;      // 128
            float* ffs  = sm + 384;      // 128
            float* hid  = sm + 512;      // 128
            float* ln2  = sm + 640;      // 128
            float* gi   = sm + 768;      // 384
            float* gh   = sm + 1152;     // 384
            float* part = sm + 1536;     // 256
            float* red  = sm + 1792;     // 8
            float* rsv  = sm + 1800;     // 1

            // phase A: reduce ya partials + rowsum
            {
                int d = t & 127, g2 = t >> 7;
                float ys = 0.0f;
                #pragma unroll 8
                for (int c = g2 * 16; c < g2 * 16 + 16; c++)
                    ys += g_Yapart[(size_t)(c * BSc + bs) * Dc + d];
                part[g2 * 128 + d] = ys;
                if (t < 32) {
                    float rv = g_rspart[t * BSc + bs];
                    #pragma unroll
                    for (int o = 16; o; o >>= 1) rv += __shfl_xor_sync(0xffffffffu, rv, o);
                    if (t == 0) rsv[0] = rv;
                }
            }
            __syncthreads();
            if (t < 128) {
                yn[t] = (part[t] + part[128 + t]) / rsv[0];
                hs[t] = g_slots[bs * Dc + t];
            }
            __syncthreads();

            // phase B: gates, 3 cols per thread
            #pragma unroll
            for (int k = 0; k < 3; k++) {
                int c = t + k * 256;
                const float* W = (c < 384) ? (g_WcT + c) : (g_WhhT + c - 384);
                const float* v = (c < 384) ? yn : hs;
                float acc = 0.0f;
                #pragma unroll 16
                for (int e = 0; e < 128; e++) acc += W[e * 384] * v[e];
                if (c < 384) gi[c] = acc; else gh[c - 384] = acc;
            }
            __syncthreads();

            // phase C: GRU + LN
            float hg = 0.0f;
            if (t < 128) {
                float gi_r = gi[t]       + g_bc[t]       + bih[t];
                float gh_r = gh[t]       + bhh[t];
                float gi_z = gi[128 + t] + g_bc[128 + t] + bih[128 + t];
                float gh_z = gh[128 + t] + bhh[128 + t];
                float gi_n = gi[256 + t] + g_bc[256 + t] + bih[256 + t];
                float gh_n = gh[256 + t] + bhh[256 + t];
                float rr = sigmoidf_(gi_r + gh_r);
                float z  = sigmoidf_(gi_z + gh_z);
                float nn = tanhf(gi_n + rr * gh_n);
                hg = (1.0f - z) * nn + z * hs[t];
                hgs[t] = hg;
            }
            {
                float v = (t < 128) ? hg : 0.0f;
                float m = bsum256(v, red) * (1.0f / 128.0f);
                float dx = (t < 128) ? (hg - m) : 0.0f;
                float var = bsum256(dx * dx, red) * (1.0f / 128.0f);
                if (t < 128) ffs[t] = dx * rsqrtf(var + 1e-5f) * g_ff[t] + be_ff[t];
            }
            __syncthreads();

            // phase D: FF1 split-K 2
            {
                int col = t & 127, h2 = t >> 7;
                float acc = 0.0f;
                #pragma unroll 8
                for (int i = 0; i < 64; i++) {
                    int d = h2 * 64 + i;
                    acc += g_W1T[d * Dc + col] * ffs[d];
                }
                part[h2 * 128 + col] = acc;
            }
            __syncthreads();
            if (t < 128) hid[t] = fmaxf(part[t] + part[128 + t] + b1[t], 0.0f);
            __syncthreads();

            // phase E: FF2
            {
                int col = t & 127, h2 = t >> 7;
                float acc = 0.0f;
                #pragma unroll 8
                for (int i = 0; i < 64; i++) {
                    int d = h2 * 64 + i;
                    acc += g_W2T[d * Dc + col] * hid[d];
                }
                part[h2 * 128 + col] = acc;
            }
            __syncthreads();
            float snew = 0.0f;
            if (t < 128) {
                snew = hgs[t] + part[t] + part[128 + t] + b2[t];
                g_slots[bs * Dc + t] = snew;
                if (emit) {
                    int bb2 = bs >> 3, s = bs & 7;
                    out_slots[(((size_t)bb2 * NFc + f) * Sc + s) * Dc + t] = snew;
                }
            }

            // phase F: LN -> qb, qt
            {
                float v = (t < 128) ? snew : 0.0f;
                float m = bsum256(v, red) * (1.0f / 128.0f);
                float dx = (t < 128) ? (snew - m) : 0.0f;
                float var = bsum256(dx * dx, red) * (1.0f / 128.0f);
                if (t < 128) ln2[t] = dx * rsqrtf(var + 1e-5f) * g_sl[t] + be_sl[t];
            }
            __syncthreads();
            {
                float qv = (t < 128) ? (g_qbv[t] * ln2[t]) : 0.0f;
                float qb = bsum256(qv, red);
                if (t == 0) g_qb[bs] = qb + g_qbb[0];
            }
            {
                int col = t & 127, h2 = t >> 7;
                float acc = 0.0f;
                #pragma unroll 8
                for (int i = 0; i < 64; i++) {
                    int e = h2 * 64 + i;
                    acc += g_MT[e * 128 + col] * ln2[e];
                }
                part[h2 * 128 + col] = acc;
            }
            __syncthreads();
            if (t < 128) g_qt[bs * Dc + t] = part[t] + part[128 + t] + g_qtb[t];
        }
        grid_barrier();
    }
}

// ---------------- launch ----------------
extern "C" void kernel_launch(void* const* d_in, const int* in_sizes, int n_in,
                              void* d_out, int out_size) {
    const float* inputs     = (const float*)d_in[0];
    const float* slots_init = (const float*)d_in[1];
    const float* Wq  = (const float*)d_in[2];
    const float* bq  = (const float*)d_in[3];
    const float* Wk  = (const float*)d_in[4];
    const float* bk  = (const float*)d_in[5];
    const float* Wv  = (const float*)d_in[6];
    const float* bv  = (const float*)d_in[7];
    const float* W1  = (const float*)d_in[8];
    const float* b1  = (const float*)d_in[9];
    const float* W2  = (const float*)d_in[10];
    const float* b2  = (const float*)d_in[11];
    const float* Wih = (const float*)d_in[12];
    const float* Whh = (const float*)d_in[13];
    const float* bih = (const float*)d_in[14];
    const float* bhh = (const float*)d_in[15];
    const float* g_in  = (const float*)d_in[16];
    const float* be_in = (const float*)d_in[17];
    const float* g_sl  = (const float*)d_in[18];
    const float* be_sl = (const float*)d_in[19];
    const float* g_ff  = (const float*)d_in[20];
    const float* be_ff = (const float*)d_in[21];

    float* out = (float*)d_out;
    float* out_slots = out;                                 // [B,NF,S,D]
    float* out_attn  = out + (size_t)Bc * NFc * Sc * Dc;    // [B,NF,S,N]

    prep_kernel<<<705, 256>>>(Wq, bq, Wk, bk, W1, W2, Wih, Whh, Wv, bv);
    main_kernel<<<NBLK, 256>>>(inputs, slots_init, out_slots, out_attn,
                               bih, bhh, g_ff, be_ff, b1, b2, g_sl, be_sl, g_in, be_in);
}